// round 8
// baseline (speedup 1.0000x reference)
#include <cuda_runtime.h>
#include <cuda_bf16.h>

#define N_GRID 64
#define N1     65
#define B_PTS  262144
#define W_FEAT 256
#define NBINS  4096          // 16^3 bins, each 4x4x4 cells, ~64 pts/bin

// ---------------- device scratch (no allocations allowed) ----------------
__device__ unsigned int g_hist[NBINS];      // histogram -> exclusive offsets (consumed by scatter)
__device__ unsigned int g_perm[B_PTS];      // sorted slot -> original point id
__device__ float4       g_sorted[B_PTS];    // sorted slot -> (t0,t1,t2, packed base|valid)

// Streaming stores (evict-first: keep L2 for the gather table)
__device__ __forceinline__ void st_cs_f4(float4* p, float4 v) {
    asm volatile("st.global.cs.v4.f32 [%0], {%1,%2,%3,%4};"
                 :: "l"(p), "f"(v.x), "f"(v.y), "f"(v.z), "f"(v.w) : "memory");
}
__device__ __forceinline__ void st_cs_f(float* p, float v) {
    asm volatile("st.global.cs.f32 [%0], %1;" :: "l"(p), "f"(v) : "memory");
}

__device__ __forceinline__ void point_math(float x0, float x1, float x2,
                                           int& i0, int& i1, int& i2,
                                           float& t0, float& t1, float& t2,
                                           bool& valid) {
    const float scale = (float)N_GRID / 2.0f;
    const float r0 = (x0 + 1.0f) * scale;
    const float r1 = (x1 + 1.0f) * scale;
    const float r2 = (x2 + 1.0f) * scale;
    valid = (r0 >= 0.0f) && (r0 <= (float)N_GRID) &&
            (r1 >= 0.0f) && (r1 <= (float)N_GRID) &&
            (r2 >= 0.0f) && (r2 <= (float)N_GRID);
    i0 = min(max((int)floorf(r0), 0), N_GRID - 1);
    i1 = min(max((int)floorf(r1), 0), N_GRID - 1);
    i2 = min(max((int)floorf(r2), 0), N_GRID - 1);
    t0 = r0 - (float)i0;
    t1 = r1 - (float)i1;
    t2 = r2 - (float)i2;
}

__device__ __forceinline__ unsigned bin_of(int i0, int i1, int i2) {
    return (unsigned)(((i0 >> 2) * 16 + (i1 >> 2)) * 16 + (i2 >> 2));
}

// ---------------- pass 0: zero histogram (4096 words) ----------------
__global__ void zero_hist_kernel() {
    g_hist[blockIdx.x * blockDim.x + threadIdx.x] = 0u;
}

// ---------------- pass 1: histogram ----------------
__global__ void hist_kernel(const float* __restrict__ x) {
    int p = blockIdx.x * blockDim.x + threadIdx.x;
    if (p >= B_PTS) return;
    int i0, i1, i2; float t0, t1, t2; bool valid;
    point_math(x[p*3+0], x[p*3+1], x[p*3+2], i0, i1, i2, t0, t1, t2, valid);
    atomicAdd(&g_hist[bin_of(i0, i1, i2)], 1u);
}

// ---------------- pass 2: single-block exclusive scan of 4096 ----------------
__global__ void __launch_bounds__(1024)
scan_kernel() {
    __shared__ unsigned int warp_sums[32];
    const int tid  = threadIdx.x;
    const int lane = tid & 31;
    const int wid  = tid >> 5;

    uint4 v = ((const uint4*)g_hist)[tid];          // 4 elems/thread
    unsigned s0 = v.x;
    unsigned s1 = s0 + v.y;
    unsigned s2 = s1 + v.z;
    unsigned total = s2 + v.w;

    // inclusive warp scan of per-thread totals
    unsigned inc = total;
    #pragma unroll
    for (int off = 1; off < 32; off <<= 1) {
        unsigned n = __shfl_up_sync(0xFFFFFFFFu, inc, off);
        if (lane >= off) inc += n;
    }
    if (lane == 31) warp_sums[wid] = inc;
    __syncthreads();
    if (wid == 0) {
        unsigned ws = warp_sums[lane];
        unsigned wi = ws;
        #pragma unroll
        for (int off = 1; off < 32; off <<= 1) {
            unsigned n = __shfl_up_sync(0xFFFFFFFFu, wi, off);
            if (lane >= off) wi += n;
        }
        warp_sums[lane] = wi - ws;                  // exclusive warp prefix
    }
    __syncthreads();
    const unsigned excl = warp_sums[wid] + (inc - total);   // exclusive thread prefix

    ((uint4*)g_hist)[tid] = make_uint4(excl, excl + s0, excl + s1, excl + s2);
}

// ---------------- pass 3: scatter into bin-sorted order ----------------
__global__ void scatter_kernel(const float* __restrict__ x) {
    int p = blockIdx.x * blockDim.x + threadIdx.x;
    if (p >= B_PTS) return;
    int i0, i1, i2; float t0, t1, t2; bool valid;
    point_math(x[p*3+0], x[p*3+1], x[p*3+2], i0, i1, i2, t0, t1, t2, valid);

    const unsigned slot = atomicAdd(&g_hist[bin_of(i0, i1, i2)], 1u);

    const int base   = (i0 * N1 + i1) * N1 + i2;    // < 2^19
    const int packed = base | (valid ? (1 << 23) : 0);

    g_perm[slot]   = (unsigned)p;
    g_sorted[slot] = make_float4(t0, t1, t2, __int_as_float(packed));
}

// ---------------- pass 4: main gather (1 warp/point, sorted order) ----------------
__global__ void __launch_bounds__(512)
trilerp_sorted_kernel(const float* __restrict__ gval,
                      const float4* __restrict__ gfeat,
                      float* __restrict__ out_val,
                      float4* __restrict__ out_feat)
{
    const int slot = (blockIdx.x * blockDim.x + threadIdx.x) >> 5;
    const int lane = threadIdx.x & 31;
    if (slot >= B_PTS) return;

    const float4 s   = __ldg(&g_sorted[slot]);      // warp-broadcast
    const unsigned p = __ldg(&g_perm[slot]);
    const int packed = __float_as_int(s.w);
    const int base   = packed & 0x7FFFFF;
    const bool valid = (packed >> 23) & 1;

    const float wx[2] = {1.0f - s.x, s.x};
    const float wy[2] = {1.0f - s.y, s.y};
    const float wz[2] = {1.0f - s.z, s.z};

    int   flat[8];
    float w[8];
#pragma unroll
    for (int c = 0; c < 8; c++) {
        const int ox = (c >> 2) & 1, oy = (c >> 1) & 1, oz = c & 1;
        flat[c] = base + (ox * N1 + oy) * N1 + oz;
        w[c]    = wx[ox] * wy[oy] * wz[oz];
    }

    float4 acc0 = make_float4(0.f, 0.f, 0.f, 0.f);
    float4 acc1 = make_float4(0.f, 0.f, 0.f, 0.f);
    float  accv = 0.f;

    if (valid) {
#pragma unroll
        for (int c = 0; c < 8; c++) {
            const float4* row = gfeat + (size_t)flat[c] * (W_FEAT / 4);
            const float4 a = __ldg(row + lane);
            const float4 b = __ldg(row + 32 + lane);
            const float  ww = w[c];
            acc0.x = fmaf(ww, a.x, acc0.x);
            acc0.y = fmaf(ww, a.y, acc0.y);
            acc0.z = fmaf(ww, a.z, acc0.z);
            acc0.w = fmaf(ww, a.w, acc0.w);
            acc1.x = fmaf(ww, b.x, acc1.x);
            acc1.y = fmaf(ww, b.y, acc1.y);
            acc1.z = fmaf(ww, b.z, acc1.z);
            acc1.w = fmaf(ww, b.w, acc1.w);
            if (lane == 0) accv = fmaf(ww, __ldg(gval + flat[c]), accv);
        }
    }

    float4* frow = out_feat + (size_t)p * (W_FEAT / 4);
    st_cs_f4(frow + lane,      acc0);
    st_cs_f4(frow + 32 + lane, acc1);
    if (lane == 0) st_cs_f(out_val + p, accv);
}

// ---------------- launch ----------------
extern "C" void kernel_launch(void* const* d_in, const int* in_sizes, int n_in,
                              void* d_out, int out_size) {
    const float* x  = (const float*)d_in[0];   // (B, 3)
    const float* gv = (const float*)d_in[1];   // (65^3, 1)
    const float* gf = (const float*)d_in[2];   // (65^3, 256)

    float* out_val  = (float*)d_out;           // (B, 1)
    float* out_feat = out_val + B_PTS;         // (B, 256)

    zero_hist_kernel<<<NBINS / 256, 256>>>();                 // 0: zero 4096 counters
    hist_kernel<<<B_PTS / 256, 256>>>(x);                     // 1: histogram
    scan_kernel<<<1, 1024>>>();                               // 2: exclusive scan (1 block)
    scatter_kernel<<<B_PTS / 256, 256>>>(x);                  // 3: bin-sorted scatter
    trilerp_sorted_kernel<<<B_PTS / 16, 512>>>(               // 4: gather
        gv, (const float4*)gf, out_val, (float4*)out_feat);
}

// round 9
// speedup vs baseline: 1.0170x; 1.0170x over previous
#include <cuda_runtime.h>
#include <cuda_bf16.h>

#define N_GRID 64
#define N1     65
#define B_PTS  262144
#define W_FEAT 256
#define NBINS  32768         // 32^3 bins, each 2x2x2 cells, ~8 pts/bin

// ---------------- device scratch (no allocations allowed) ----------------
__device__ unsigned int g_hist[NBINS];      // histogram -> exclusive offsets (consumed by scatter)
__device__ unsigned int g_perm[B_PTS];      // sorted slot -> original point id
__device__ float4       g_sorted[B_PTS];    // sorted slot -> (t0,t1,t2, packed base|valid)

// Streaming stores (evict-first: keep L2 for the gather table)
__device__ __forceinline__ void st_cs_f4(float4* p, float4 v) {
    asm volatile("st.global.cs.v4.f32 [%0], {%1,%2,%3,%4};"
                 :: "l"(p), "f"(v.x), "f"(v.y), "f"(v.z), "f"(v.w) : "memory");
}
__device__ __forceinline__ void st_cs_f(float* p, float v) {
    asm volatile("st.global.cs.f32 [%0], %1;" :: "l"(p), "f"(v) : "memory");
}

__device__ __forceinline__ void point_math(float x0, float x1, float x2,
                                           int& i0, int& i1, int& i2,
                                           float& t0, float& t1, float& t2,
                                           bool& valid) {
    const float scale = (float)N_GRID / 2.0f;
    const float r0 = (x0 + 1.0f) * scale;
    const float r1 = (x1 + 1.0f) * scale;
    const float r2 = (x2 + 1.0f) * scale;
    valid = (r0 >= 0.0f) && (r0 <= (float)N_GRID) &&
            (r1 >= 0.0f) && (r1 <= (float)N_GRID) &&
            (r2 >= 0.0f) && (r2 <= (float)N_GRID);
    i0 = min(max((int)floorf(r0), 0), N_GRID - 1);
    i1 = min(max((int)floorf(r1), 0), N_GRID - 1);
    i2 = min(max((int)floorf(r2), 0), N_GRID - 1);
    t0 = r0 - (float)i0;
    t1 = r1 - (float)i1;
    t2 = r2 - (float)i2;
}

__device__ __forceinline__ unsigned bin_of(int i0, int i1, int i2) {
    return (unsigned)(((i0 >> 1) * 32 + (i1 >> 1)) * 32 + (i2 >> 1));
}

// ---------------- pass 0: zero histogram (32768 words) ----------------
__global__ void zero_hist_kernel() {
    g_hist[blockIdx.x * blockDim.x + threadIdx.x] = 0u;
}

// ---------------- pass 1: histogram ----------------
__global__ void hist_kernel(const float* __restrict__ x) {
    int p = blockIdx.x * blockDim.x + threadIdx.x;
    if (p >= B_PTS) return;
    int i0, i1, i2; float t0, t1, t2; bool valid;
    point_math(x[p*3+0], x[p*3+1], x[p*3+2], i0, i1, i2, t0, t1, t2, valid);
    atomicAdd(&g_hist[bin_of(i0, i1, i2)], 1u);
}

// ---------------- pass 2: single-block exclusive scan of 32768 ----------------
// 1024 threads x 32 contiguous elems each (8 uint4). Sequential scan in regs,
// then warp scan of thread-totals, then block scan of warp-totals.
__global__ void __launch_bounds__(1024)
scan_kernel() {
    __shared__ unsigned int warp_sums[32];
    const int tid  = threadIdx.x;
    const int lane = tid & 31;
    const int wid  = tid >> 5;

    uint4 v[8];
    #pragma unroll
    for (int j = 0; j < 8; j++) v[j] = ((const uint4*)g_hist)[tid * 8 + j];

    // sequential exclusive scan over 32 elems; keep running total
    unsigned run = 0;
    unsigned ex[32];
    #pragma unroll
    for (int j = 0; j < 8; j++) {
        ex[j*4+0] = run; run += v[j].x;
        ex[j*4+1] = run; run += v[j].y;
        ex[j*4+2] = run; run += v[j].z;
        ex[j*4+3] = run; run += v[j].w;
    }
    const unsigned total = run;

    // inclusive warp scan of thread totals
    unsigned inc = total;
    #pragma unroll
    for (int off = 1; off < 32; off <<= 1) {
        unsigned n = __shfl_up_sync(0xFFFFFFFFu, inc, off);
        if (lane >= off) inc += n;
    }
    if (lane == 31) warp_sums[wid] = inc;
    __syncthreads();
    if (wid == 0) {
        unsigned ws = warp_sums[lane];
        unsigned wi = ws;
        #pragma unroll
        for (int off = 1; off < 32; off <<= 1) {
            unsigned n = __shfl_up_sync(0xFFFFFFFFu, wi, off);
            if (lane >= off) wi += n;
        }
        warp_sums[lane] = wi - ws;              // exclusive warp prefix
    }
    __syncthreads();
    const unsigned base = warp_sums[wid] + (inc - total);   // exclusive thread prefix

    #pragma unroll
    for (int j = 0; j < 8; j++) {
        uint4 o;
        o.x = base + ex[j*4+0];
        o.y = base + ex[j*4+1];
        o.z = base + ex[j*4+2];
        o.w = base + ex[j*4+3];
        ((uint4*)g_hist)[tid * 8 + j] = o;
    }
}

// ---------------- pass 3: scatter into bin-sorted order ----------------
__global__ void scatter_kernel(const float* __restrict__ x) {
    int p = blockIdx.x * blockDim.x + threadIdx.x;
    if (p >= B_PTS) return;
    int i0, i1, i2; float t0, t1, t2; bool valid;
    point_math(x[p*3+0], x[p*3+1], x[p*3+2], i0, i1, i2, t0, t1, t2, valid);

    const unsigned slot = atomicAdd(&g_hist[bin_of(i0, i1, i2)], 1u);

    const int base   = (i0 * N1 + i1) * N1 + i2;    // < 2^19
    const int packed = base | (valid ? (1 << 23) : 0);

    g_perm[slot]   = (unsigned)p;
    g_sorted[slot] = make_float4(t0, t1, t2, __int_as_float(packed));
}

// ---------------- pass 4: main gather (1 warp/point, sorted order) ----------------
__global__ void __launch_bounds__(512)
trilerp_sorted_kernel(const float* __restrict__ gval,
                      const float4* __restrict__ gfeat,
                      float* __restrict__ out_val,
                      float4* __restrict__ out_feat)
{
    const int slot = (blockIdx.x * blockDim.x + threadIdx.x) >> 5;
    const int lane = threadIdx.x & 31;
    if (slot >= B_PTS) return;

    const float4 s   = __ldg(&g_sorted[slot]);      // warp-broadcast
    const unsigned p = __ldg(&g_perm[slot]);
    const int packed = __float_as_int(s.w);
    const int base   = packed & 0x7FFFFF;
    const bool valid = (packed >> 23) & 1;

    const float wx[2] = {1.0f - s.x, s.x};
    const float wy[2] = {1.0f - s.y, s.y};
    const float wz[2] = {1.0f - s.z, s.z};

    int   flat[8];
    float w[8];
#pragma unroll
    for (int c = 0; c < 8; c++) {
        const int ox = (c >> 2) & 1, oy = (c >> 1) & 1, oz = c & 1;
        flat[c] = base + (ox * N1 + oy) * N1 + oz;
        w[c]    = wx[ox] * wy[oy] * wz[oz];
    }

    float4 acc0 = make_float4(0.f, 0.f, 0.f, 0.f);
    float4 acc1 = make_float4(0.f, 0.f, 0.f, 0.f);
    float  accv = 0.f;

    if (valid) {
#pragma unroll
        for (int c = 0; c < 8; c++) {
            const float4* row = gfeat + (size_t)flat[c] * (W_FEAT / 4);
            const float4 a = __ldg(row + lane);
            const float4 b = __ldg(row + 32 + lane);
            const float  ww = w[c];
            acc0.x = fmaf(ww, a.x, acc0.x);
            acc0.y = fmaf(ww, a.y, acc0.y);
            acc0.z = fmaf(ww, a.z, acc0.z);
            acc0.w = fmaf(ww, a.w, acc0.w);
            acc1.x = fmaf(ww, b.x, acc1.x);
            acc1.y = fmaf(ww, b.y, acc1.y);
            acc1.z = fmaf(ww, b.z, acc1.z);
            acc1.w = fmaf(ww, b.w, acc1.w);
            if (lane == 0) accv = fmaf(ww, __ldg(gval + flat[c]), accv);
        }
    }

    float4* frow = out_feat + (size_t)p * (W_FEAT / 4);
    st_cs_f4(frow + lane,      acc0);
    st_cs_f4(frow + 32 + lane, acc1);
    if (lane == 0) st_cs_f(out_val + p, accv);
}

// ---------------- launch ----------------
extern "C" void kernel_launch(void* const* d_in, const int* in_sizes, int n_in,
                              void* d_out, int out_size) {
    const float* x  = (const float*)d_in[0];   // (B, 3)
    const float* gv = (const float*)d_in[1];   // (65^3, 1)
    const float* gf = (const float*)d_in[2];   // (65^3, 256)

    float* out_val  = (float*)d_out;           // (B, 1)
    float* out_feat = out_val + B_PTS;         // (B, 256)

    zero_hist_kernel<<<NBINS / 256, 256>>>();                 // 0: zero 32768 counters
    hist_kernel<<<B_PTS / 256, 256>>>(x);                     // 1: histogram
    scan_kernel<<<1, 1024>>>();                               // 2: exclusive scan (1 block)
    scatter_kernel<<<B_PTS / 256, 256>>>(x);                  // 3: bin-sorted scatter
    trilerp_sorted_kernel<<<B_PTS / 16, 512>>>(               // 4: gather
        gv, (const float4*)gf, out_val, (float4*)out_feat);
}